// round 10
// baseline (speedup 1.0000x reference)
#include <cuda_runtime.h>
#include <cuda_bf16.h>
#include <cstdint>
#include <cstddef>

#define NN 8192
#define INF 512
#define OF 64
#define SPLITJ 8
#define JCHUNK (NN / SPLITJ)

// ---------------- device scratch (no allocations allowed) ----------------
__device__ float g_WH[NN * OF];
__device__ float g_wh1[NN], g_wh2[NN];
__device__ float g_e1[NN], g_f1[NN], g_e2[NN], g_f2[NN];
__device__ uint4 g_Bf[(NN / 32) * 16 * 32];          // B fragments, 2MB
__device__ float g_num[(size_t)SPLITJ * NN * OF];    // 16MB partial numerators
__device__ float g_den[SPLITJ * NN];

// ---------------- helpers ----------------
// pack two f32 -> bf16x2; FIRST arg lands in the LOW half
__device__ __forceinline__ uint32_t pkbf(float lo, float hi) {
    uint32_t r;
    asm("cvt.rn.bf16x2.f32 %0, %1, %2;" : "=r"(r) : "f"(hi), "f"(lo));
    return r;
}
// hi/lo split of a pair: h = bf16x2(v), l = bf16x2(v - upcast(h))
__device__ __forceinline__ void split2(float x, float y, uint32_t& h, uint32_t& l) {
    h = pkbf(x, y);
    float lx = x - __uint_as_float(h << 16);
    float ly = y - __uint_as_float(h & 0xffff0000u);
    l = pkbf(lx, ly);
}
__device__ __forceinline__ void mma_bf16(float* c, const uint32_t* a,
                                         uint32_t b0, uint32_t b1) {
    asm volatile(
        "mma.sync.aligned.m16n8k16.row.col.f32.bf16.bf16.f32 "
        "{%0,%1,%2,%3}, {%4,%5,%6,%7}, {%8,%9}, {%0,%1,%2,%3};"
        : "+f"(c[0]), "+f"(c[1]), "+f"(c[2]), "+f"(c[3])
        : "r"(a[0]), "r"(a[1]), "r"(a[2]), "r"(a[3]), "r"(b0), "r"(b1));
}
#define ONESB 0x3F803F80u

// ---------------- kernel 1: WH = h @ W (fp32 exact) ----------------
__global__ void gemm_wh(const float* __restrict__ h, const float* __restrict__ Wm) {
    __shared__ float hs[64][36];
    __shared__ float Ws[32][68];
    const int tid = threadIdx.x;
    const int ibase = blockIdx.x * 64;
    const int tx = tid & 15, ty = tid >> 4;
    const int r0 = ty * 4, c0 = tx * 4;
    float acc[4][4] = {};
    for (int kt = 0; kt < INF; kt += 32) {
        __syncthreads();
#pragma unroll
        for (int q = 0; q < 2; q++) {
            int idx = tid + q * 256;
            int row = idx >> 3, kq = idx & 7;
            *(float4*)&hs[row][kq * 4] = *(const float4*)&h[(size_t)(ibase + row) * INF + kt + kq * 4];
            int kr = idx >> 4, cq = idx & 15;
            *(float4*)&Ws[kr][cq * 4] = *(const float4*)&Wm[(size_t)(kt + kr) * OF + cq * 4];
        }
        __syncthreads();
#pragma unroll
        for (int k = 0; k < 32; k++) {
            float4 b = *(const float4*)&Ws[k][c0];
#pragma unroll
            for (int r = 0; r < 4; r++) {
                float av = hs[r0 + r][k];
                acc[r][0] += av * b.x; acc[r][1] += av * b.y;
                acc[r][2] += av * b.z; acc[r][3] += av * b.w;
            }
        }
    }
#pragma unroll
    for (int r = 0; r < 4; r++)
        *(float4*)&g_WH[(size_t)(ibase + r0 + r) * OF + c0] =
            make_float4(acc[r][0], acc[r][1], acc[r][2], acc[r][3]);
}

// ---------------- kernel 2: per-row stats (factored exp trick) ----------------
__global__ void row_stats(const float* __restrict__ a) {
    const int lane = threadIdx.x & 31;
    const int wid = threadIdx.x >> 5;
    const int row = blockIdx.x * 8 + wid;
    float v0 = g_WH[row * OF + lane];
    float v1 = g_WH[row * OF + 32 + lane];
    float p1 = v0 * a[lane] + v1 * a[lane + 32];
    float p2 = v0 * a[64 + lane] + v1 * a[96 + lane];
#pragma unroll
    for (int off = 16; off; off >>= 1) {
        p1 += __shfl_xor_sync(0xffffffffu, p1, off);
        p2 += __shfl_xor_sync(0xffffffffu, p2, off);
    }
    if (lane == 0) {
        g_wh1[row] = p1; g_wh2[row] = p2;
        g_e1[row] = expf(p1); g_f1[row] = expf(0.01f * p1);
        g_e2[row] = expf(p2); g_f2[row] = expf(0.01f * p2);
    }
}

// ---------------- kernel 2b: B (=WH) -> mma fragments, bf16 hi/lo ----------------
__global__ void wht_prep() {
    int t = blockIdx.x * 256 + threadIdx.x;        // 0 .. 131071
    int lane = t & 31;
    int n = (t >> 5) & 7;
    int s = (t >> 8) & 1;
    int c = t >> 9;
    int j0 = c * 32 + s * 16 + 2 * (lane & 3);
    int f = n * 8 + (lane >> 2);
    float v00 = g_WH[(size_t)j0 * OF + f];
    float v01 = g_WH[(size_t)(j0 + 1) * OF + f];
    float v10 = g_WH[(size_t)(j0 + 8) * OF + f];
    float v11 = g_WH[(size_t)(j0 + 9) * OF + f];
    uint32_t bh0, bl0, bh1, bl1;
    split2(v00, v01, bh0, bl0);
    split2(v10, v11, bh1, bl1);
    g_Bf[t] = make_uint4(bh0, bh1, bl0, bl1);
}

// ---------------- kernel 3: fused masked-softmax attention GEMM (HMMA) ----------------
__global__ void __launch_bounds__(128, 4) attn(const int* __restrict__ adj) {
    __shared__ float ws[128][36];                  // warp-private 32-row slabs
    __shared__ float s_rw1[128], s_re1[128], s_rf1[128];

    const int tid = threadIdx.x;
    const int lane = tid & 31;
    const int warp = tid >> 5;
    const int ibase = blockIdx.x * 128;
    const int split = blockIdx.y;
    {
        int gi = ibase + tid;
        s_rw1[tid] = g_wh1[gi]; s_re1[tid] = g_e1[gi]; s_rf1[tid] = g_f1[gi];
    }
    __syncthreads();

    const int g = lane >> 2;
    const int qp = lane & 3;
    float acc[2][8][4];
    float den[2][4];
#pragma unroll
    for (int m = 0; m < 2; m++) {
#pragma unroll
        for (int n = 0; n < 8; n++)
#pragma unroll
            for (int q = 0; q < 4; q++) acc[m][n][q] = 0.f;
#pragma unroll
        for (int q = 0; q < 4; q++) den[m][q] = 0.f;
    }

    const int jbase = split * JCHUNK;
    for (int jt = jbase; jt < jbase + JCHUNK; jt += 32) {
        // ---- weight generation (warp-private rows, no cross-lane reduce) ----
        const int j = jt + lane;
        const float w2j = g_wh2[j];
        const float e2j = g_e2[j];
        const float f2j = g_f2[j];
        const int* ap = adj + (size_t)(ibase + warp * 32) * NN + j;
#pragma unroll 8
        for (int r = 0; r < 32; r++) {
            int av = __ldcs(ap + (size_t)r * NN);
            int il = warp * 32 + r;
            float sv = s_rw1[il] + w2j;
            float w = (sv > 0.f) ? s_re1[il] * e2j : s_rf1[il] * f2j;
            ws[il][lane] = av ? w : 0.f;
        }
        __syncwarp();

        // ---- hi/lo bf16 MMA, pass-major to break RAW chains ----
        const uint4* bp = g_Bf + ((size_t)(jt >> 5) * 16) * 32 + lane;
#pragma unroll
        for (int s = 0; s < 2; s++) {
            // prefetch all 8 B fragments for this k-step
            uint4 B[8];
#pragma unroll
            for (int n = 0; n < 8; n++) B[n] = bp[(s * 8 + n) * 32];

            uint32_t Ah[2][4], Al[2][4];
            const int k0 = s * 16 + qp * 2;
#pragma unroll
            for (int m = 0; m < 2; m++) {
                const int ra = warp * 32 + m * 16 + g;
                float2 p0 = *(const float2*)&ws[ra][k0];
                float2 p1 = *(const float2*)&ws[ra + 8][k0];
                float2 p2 = *(const float2*)&ws[ra][k0 + 8];
                float2 p3 = *(const float2*)&ws[ra + 8][k0 + 8];
                split2(p0.x, p0.y, Ah[m][0], Al[m][0]);
                split2(p1.x, p1.y, Ah[m][1], Al[m][1]);
                split2(p2.x, p2.y, Ah[m][2], Al[m][2]);
                split2(p3.x, p3.y, Ah[m][3], Al[m][3]);
            }
            // pass 1: Ah @ Bh  (+ den hi via ones column)
#pragma unroll
            for (int n = 0; n < 8; n++) {
                mma_bf16(acc[0][n], Ah[0], B[n].x, B[n].y);
                mma_bf16(acc[1][n], Ah[1], B[n].x, B[n].y);
            }
            mma_bf16(den[0], Ah[0], ONESB, ONESB);
            mma_bf16(den[1], Ah[1], ONESB, ONESB);
            // pass 2: Al @ Bh  (+ den lo)
#pragma unroll
            for (int n = 0; n < 8; n++) {
                mma_bf16(acc[0][n], Al[0], B[n].x, B[n].y);
                mma_bf16(acc[1][n], Al[1], B[n].x, B[n].y);
            }
            mma_bf16(den[0], Al[0], ONESB, ONESB);
            mma_bf16(den[1], Al[1], ONESB, ONESB);
            // pass 3: Ah @ Bl
#pragma unroll
            for (int n = 0; n < 8; n++) {
                mma_bf16(acc[0][n], Ah[0], B[n].z, B[n].w);
                mma_bf16(acc[1][n], Ah[1], B[n].z, B[n].w);
            }
        }
        __syncwarp();   // ws reuse next iteration (warp-private)
    }

    // ---- epilogue ----
    if (qp == 0) {
#pragma unroll
        for (int m = 0; m < 2; m++) {
            int row = ibase + warp * 32 + m * 16 + g;
            g_den[split * NN + row] = den[m][0];
            g_den[split * NN + row + 8] = den[m][2];
        }
    }
#pragma unroll
    for (int m = 0; m < 2; m++) {
#pragma unroll
        for (int n = 0; n < 8; n++) {
            int row = ibase + warp * 32 + m * 16 + g;
            int f = n * 8 + qp * 2;
            size_t base = ((size_t)split * NN + row) * OF + f;
            *(float2*)&g_num[base] = make_float2(acc[m][n][0], acc[m][n][1]);
            *(float2*)&g_num[base + 8 * OF] = make_float2(acc[m][n][2], acc[m][n][3]);
        }
    }
}

// ---------------- kernel 4: reduce partials, divide, ELU ----------------
__global__ void finalize_k(float* __restrict__ out) {
    int idx = blockIdx.x * 256 + threadIdx.x;
    int i = idx >> 6, f = idx & 63;
    float num = 0.f, den = 0.f;
#pragma unroll
    for (int s = 0; s < SPLITJ; s++) {
        num += g_num[((size_t)s * NN + i) * OF + f];
        den += g_den[s * NN + i];
    }
    float x = num / den;
    out[idx] = (x > 0.f) ? x : expm1f(x);
}

// ---------------- launch ----------------
extern "C" void kernel_launch(void* const* d_in, const int* in_sizes, int n_in,
                              void* d_out, int out_size) {
    const float* h = nullptr; const int* adj = nullptr;
    const float* Wm = nullptr; const float* a = nullptr;
    for (int i = 0; i < n_in; i++) {
        switch (in_sizes[i]) {
            case NN * INF: h = (const float*)d_in[i]; break;
            case NN * NN:  adj = (const int*)d_in[i]; break;
            case INF * OF: Wm = (const float*)d_in[i]; break;
            case 2 * OF:   a = (const float*)d_in[i]; break;
            default: break;
        }
    }
    gemm_wh<<<NN / 64, 256>>>(h, Wm);
    row_stats<<<NN / 8, 256>>>(a);
    wht_prep<<<512, 256>>>();
    dim3 g(NN / 128, SPLITJ);
    attn<<<g, 128>>>(adj);
    finalize_k<<<(NN * OF) / 256, 256>>>((float*)d_out);
}

// round 11
// speedup vs baseline: 1.6078x; 1.6078x over previous
#include <cuda_runtime.h>
#include <cuda_bf16.h>
#include <cstdint>
#include <cstddef>

#define NN 8192
#define INF 512
#define OF 64
#define SPLITJ 8
#define JCHUNK (NN / SPLITJ)
#define NKT (JCHUNK / 32)

// ---------------- device scratch (no allocations allowed) ----------------
__device__ float g_WH[NN * OF];
__device__ float g_wh1[NN], g_wh2[NN];
__device__ float g_e1[NN], g_f1[NN], g_e2[NN], g_f2[NN];
__device__ uint4 g_Bf[(NN / 32) * 16 * 32];          // B fragments, 2MB (L2-resident)
__device__ float g_num[(size_t)SPLITJ * NN * OF];    // 16MB partial numerators
__device__ float g_den[SPLITJ * NN];

// ---------------- helpers ----------------
__device__ __forceinline__ uint32_t pkbf(float lo, float hi) {
    uint32_t r;
    asm("cvt.rn.bf16x2.f32 %0, %1, %2;" : "=r"(r) : "f"(hi), "f"(lo));
    return r;
}
__device__ __forceinline__ void split2(float x, float y, uint32_t& h, uint32_t& l) {
    h = pkbf(x, y);
    float lx = x - __uint_as_float(h << 16);
    float ly = y - __uint_as_float(h & 0xffff0000u);
    l = pkbf(lx, ly);
}
// weight pair for one (row, col-pair): mask + factored-exp leaky-softmax weight, then hi/lo split
__device__ __forceinline__ void wpair(int2 a, float rw, float re, float rf,
                                      float2 w2, float2 e2, float2 f2,
                                      uint32_t& h, uint32_t& l) {
    float s0 = rw + w2.x, s1 = rw + w2.y;
    float w0 = a.x ? ((s0 > 0.f) ? re * e2.x : rf * f2.x) : 0.f;
    float w1 = a.y ? ((s1 > 0.f) ? re * e2.y : rf * f2.y) : 0.f;
    split2(w0, w1, h, l);
}
__device__ __forceinline__ void mma_bf16(float* c, const uint32_t* a,
                                         uint32_t b0, uint32_t b1) {
    asm volatile(
        "mma.sync.aligned.m16n8k16.row.col.f32.bf16.bf16.f32 "
        "{%0,%1,%2,%3}, {%4,%5,%6,%7}, {%8,%9}, {%0,%1,%2,%3};"
        : "+f"(c[0]), "+f"(c[1]), "+f"(c[2]), "+f"(c[3])
        : "r"(a[0]), "r"(a[1]), "r"(a[2]), "r"(a[3]), "r"(b0), "r"(b1));
}
#define ONESB 0x3F803F80u

// ---------------- kernel 1: WH = h @ W (fp32 exact) ----------------
__global__ void gemm_wh(const float* __restrict__ h, const float* __restrict__ Wm) {
    __shared__ float hs[64][36];
    __shared__ float Ws[32][68];
    const int tid = threadIdx.x;
    const int ibase = blockIdx.x * 64;
    const int tx = tid & 15, ty = tid >> 4;
    const int r0 = ty * 4, c0 = tx * 4;
    float acc[4][4] = {};
    for (int kt = 0; kt < INF; kt += 32) {
        __syncthreads();
#pragma unroll
        for (int q = 0; q < 2; q++) {
            int idx = tid + q * 256;
            int row = idx >> 3, kq = idx & 7;
            *(float4*)&hs[row][kq * 4] = *(const float4*)&h[(size_t)(ibase + row) * INF + kt + kq * 4];
            int kr = idx >> 4, cq = idx & 15;
            *(float4*)&Ws[kr][cq * 4] = *(const float4*)&Wm[(size_t)(kt + kr) * OF + cq * 4];
        }
        __syncthreads();
#pragma unroll
        for (int k = 0; k < 32; k++) {
            float4 b = *(const float4*)&Ws[k][c0];
#pragma unroll
            for (int r = 0; r < 4; r++) {
                float av = hs[r0 + r][k];
                acc[r][0] += av * b.x; acc[r][1] += av * b.y;
                acc[r][2] += av * b.z; acc[r][3] += av * b.w;
            }
        }
    }
#pragma unroll
    for (int r = 0; r < 4; r++)
        *(float4*)&g_WH[(size_t)(ibase + r0 + r) * OF + c0] =
            make_float4(acc[r][0], acc[r][1], acc[r][2], acc[r][3]);
}

// ---------------- kernel 2: per-row stats (factored exp trick) ----------------
__global__ void row_stats(const float* __restrict__ a) {
    const int lane = threadIdx.x & 31;
    const int wid = threadIdx.x >> 5;
    const int row = blockIdx.x * 8 + wid;
    float v0 = g_WH[row * OF + lane];
    float v1 = g_WH[row * OF + 32 + lane];
    float p1 = v0 * a[lane] + v1 * a[lane + 32];
    float p2 = v0 * a[64 + lane] + v1 * a[96 + lane];
#pragma unroll
    for (int off = 16; off; off >>= 1) {
        p1 += __shfl_xor_sync(0xffffffffu, p1, off);
        p2 += __shfl_xor_sync(0xffffffffu, p2, off);
    }
    if (lane == 0) {
        g_wh1[row] = p1; g_wh2[row] = p2;
        g_e1[row] = expf(p1); g_f1[row] = expf(0.01f * p1);
        g_e2[row] = expf(p2); g_f2[row] = expf(0.01f * p2);
    }
}

// ---------------- kernel 2b: B (=WH) -> mma fragments, bf16 hi/lo ----------------
__global__ void wht_prep() {
    int t = blockIdx.x * 256 + threadIdx.x;        // 0 .. 131071
    int lane = t & 31;
    int n = (t >> 5) & 7;
    int s = (t >> 8) & 1;
    int c = t >> 9;
    int j0 = c * 32 + s * 16 + 2 * (lane & 3);
    int f = n * 8 + (lane >> 2);
    float v00 = g_WH[(size_t)j0 * OF + f];
    float v01 = g_WH[(size_t)(j0 + 1) * OF + f];
    float v10 = g_WH[(size_t)(j0 + 8) * OF + f];
    float v11 = g_WH[(size_t)(j0 + 9) * OF + f];
    uint32_t bh0, bl0, bh1, bl1;
    split2(v00, v01, bh0, bl0);
    split2(v10, v11, bh1, bl1);
    g_Bf[t] = make_uint4(bh0, bh1, bl0, bl1);
}

// ---------------- kernel 3: fragment-direct fused attention GEMM ----------------
// warp owns 16 rows; no shared memory, no syncs; adjacency prefetched 1 tile ahead
__global__ void __launch_bounds__(128, 4) attn(const int* __restrict__ adj) {
    const int tid = threadIdx.x;
    const int lane = tid & 31;
    const int warp = tid >> 5;
    const int ibase = blockIdx.x * 64;
    const int split = blockIdx.y;
    const int g = lane >> 2, qp = lane & 3;
    const int rg = ibase + warp * 16 + g;
    const int rg8 = rg + 8;

    // per-row params live in registers for the whole kernel
    const float rwa = g_wh1[rg], rea = g_e1[rg], rfa = g_f1[rg];
    const float rwb = g_wh1[rg8], reb = g_e1[rg8], rfb = g_f1[rg8];

    float acc[8][4];
    float den[4];
#pragma unroll
    for (int n = 0; n < 8; n++)
#pragma unroll
        for (int q = 0; q < 4; q++) acc[n][q] = 0.f;
#pragma unroll
    for (int q = 0; q < 4; q++) den[q] = 0.f;

    const int jbase = split * JCHUNK;
    const int* apA = adj + (size_t)rg * NN + 2 * qp;
    const int* apB = adj + (size_t)rg8 * NN + 2 * qp;

    // adjacency in fragment layout: av[row(0=g,1=g+8)][colgroup u -> cols 2qp+8u .. +1]
    int2 av[2][4];
#pragma unroll
    for (int u = 0; u < 4; u++) {
        av[0][u] = __ldcs((const int2*)(apA + jbase + u * 8));
        av[1][u] = __ldcs((const int2*)(apB + jbase + u * 8));
    }

    for (int t = 0; t < NKT; t++) {
        const int jt = jbase + t * 32;
        const int jn = (t + 1 < NKT) ? jt + 32 : jbase;   // clamp (redundant reload, discarded)
        int2 avn[2][4];
#pragma unroll
        for (int u = 0; u < 4; u++) {                      // prefetch next tile (hides DRAM)
            avn[0][u] = __ldcs((const int2*)(apA + jn + u * 8));
            avn[1][u] = __ldcs((const int2*)(apB + jn + u * 8));
        }
        const uint4* bp = g_Bf + (size_t)(jt >> 5) * 512 + lane;

#pragma unroll
        for (int s = 0; s < 2; s++) {
            const int c0 = jt + s * 16 + 2 * qp;
            float2 w2a = *(const float2*)&g_wh2[c0];
            float2 e2a = *(const float2*)&g_e2[c0];
            float2 f2a = *(const float2*)&g_f2[c0];
            float2 w2b = *(const float2*)&g_wh2[c0 + 8];
            float2 e2b = *(const float2*)&g_e2[c0 + 8];
            float2 f2b = *(const float2*)&g_f2[c0 + 8];

            uint32_t Ah[4], Al[4];
            wpair(av[0][2 * s],     rwa, rea, rfa, w2a, e2a, f2a, Ah[0], Al[0]);
            wpair(av[1][2 * s],     rwb, reb, rfb, w2a, e2a, f2a, Ah[1], Al[1]);
            wpair(av[0][2 * s + 1], rwa, rea, rfa, w2b, e2b, f2b, Ah[2], Al[2]);
            wpair(av[1][2 * s + 1], rwb, reb, rfb, w2b, e2b, f2b, Ah[3], Al[3]);

            uint4 B0[4];
#pragma unroll
            for (int n = 0; n < 4; n++) B0[n] = bp[(s * 8 + n) * 32];
#pragma unroll
            for (int n = 0; n < 4; n++) mma_bf16(acc[n], Ah, B0[n].x, B0[n].y);
            mma_bf16(den, Ah, ONESB, ONESB);
            uint4 B1[4];
#pragma unroll
            for (int n = 0; n < 4; n++) B1[n] = bp[(s * 8 + 4 + n) * 32];
#pragma unroll
            for (int n = 0; n < 4; n++) mma_bf16(acc[n], Al, B0[n].x, B0[n].y);
            mma_bf16(den, Al, ONESB, ONESB);
#pragma unroll
            for (int n = 0; n < 4; n++) mma_bf16(acc[n], Ah, B0[n].z, B0[n].w);
#pragma unroll
            for (int n = 0; n < 4; n++) mma_bf16(acc[4 + n], Ah, B1[n].x, B1[n].y);
#pragma unroll
            for (int n = 0; n < 4; n++) mma_bf16(acc[4 + n], Al, B1[n].x, B1[n].y);
#pragma unroll
            for (int n = 0; n < 4; n++) mma_bf16(acc[4 + n], Ah, B1[n].z, B1[n].w);
        }
#pragma unroll
        for (int u = 0; u < 4; u++) { av[0][u] = avn[0][u]; av[1][u] = avn[1][u]; }
    }

    // ---- epilogue ----
    if (qp == 0) {
        g_den[split * NN + rg] = den[0];
        g_den[split * NN + rg8] = den[2];
    }
#pragma unroll
    for (int n = 0; n < 8; n++) {
        size_t ba = ((size_t)split * NN + rg) * OF + n * 8 + qp * 2;
        *(float2*)&g_num[ba] = make_float2(acc[n][0], acc[n][1]);
        *(float2*)&g_num[ba + 8 * (size_t)OF] = make_float2(acc[n][2], acc[n][3]);
    }
}

// ---------------- kernel 4: reduce partials, divide, ELU ----------------
__global__ void finalize_k(float* __restrict__ out) {
    int idx = blockIdx.x * 256 + threadIdx.x;
    int i = idx >> 6, f = idx & 63;
    float num = 0.f, den = 0.f;
#pragma unroll
    for (int s = 0; s < SPLITJ; s++) {
        num += g_num[((size_t)s * NN + i) * OF + f];
        den += g_den[s * NN + i];
    }
    float x = num / den;
    out[idx] = (x > 0.f) ? x : expm1f(x);
}

// ---------------- launch ----------------
extern "C" void kernel_launch(void* const* d_in, const int* in_sizes, int n_in,
                              void* d_out, int out_size) {
    const float* h = nullptr; const int* adj = nullptr;
    const float* Wm = nullptr; const float* a = nullptr;
    for (int i = 0; i < n_in; i++) {
        switch (in_sizes[i]) {
            case NN * INF: h = (const float*)d_in[i]; break;
            case NN * NN:  adj = (const int*)d_in[i]; break;
            case INF * OF: Wm = (const float*)d_in[i]; break;
            case 2 * OF:   a = (const float*)d_in[i]; break;
            default: break;
        }
    }
    gemm_wh<<<NN / 64, 256>>>(h, Wm);
    row_stats<<<NN / 8, 256>>>(a);
    wht_prep<<<512, 256>>>();
    dim3 g(NN / 64, SPLITJ);
    attn<<<g, 128>>>(adj);
    finalize_k<<<(NN * OF) / 256, 256>>>((float*)d_out);
}

// round 13
// speedup vs baseline: 1.7759x; 1.1046x over previous
#include <cuda_runtime.h>
#include <cuda_bf16.h>
#include <cstdint>
#include <cstddef>

#define NN 8192
#define INF 512
#define OF 64
#define SPLITJ 8
#define JCHUNK (NN / SPLITJ)
#define NKT (JCHUNK / 32)

// ---------------- device scratch (no allocations allowed) ----------------
__device__ float g_WH[NN * OF];
__device__ float g_wh1[NN], g_wh2[NN];
__device__ float g_e1[NN], g_f1[NN], g_e2[NN], g_f2[NN];
__device__ uint4 g_Bf[(NN / 32) * 16 * 32];          // B fragments, 2MB (L2-resident)
__device__ float g_num[(size_t)SPLITJ * NN * OF];    // 16MB partial numerators
__device__ float g_den[SPLITJ * NN];

// ---------------- helpers ----------------
__device__ __forceinline__ uint32_t pkbf(float lo, float hi) {
    uint32_t r;
    asm("cvt.rn.bf16x2.f32 %0, %1, %2;" : "=r"(r) : "f"(hi), "f"(lo));
    return r;
}
__device__ __forceinline__ void split2(float x, float y, uint32_t& h, uint32_t& l) {
    h = pkbf(x, y);
    float lx = x - __uint_as_float(h << 16);
    float ly = y - __uint_as_float(h & 0xffff0000u);
    l = pkbf(lx, ly);
}
__device__ __forceinline__ void wpair(int2 a, float rw, float re, float rf,
                                      float2 w2, float2 e2, float2 f2,
                                      uint32_t& h, uint32_t& l) {
    float s0 = rw + w2.x, s1 = rw + w2.y;
    float w0 = a.x ? ((s0 > 0.f) ? re * e2.x : rf * f2.x) : 0.f;
    float w1 = a.y ? ((s1 > 0.f) ? re * e2.y : rf * f2.y) : 0.f;
    split2(w0, w1, h, l);
}
__device__ __forceinline__ void mma_bf16(float* c, const uint32_t* a,
                                         uint32_t b0, uint32_t b1) {
    asm volatile(
        "mma.sync.aligned.m16n8k16.row.col.f32.bf16.bf16.f32 "
        "{%0,%1,%2,%3}, {%4,%5,%6,%7}, {%8,%9}, {%0,%1,%2,%3};"
        : "+f"(c[0]), "+f"(c[1]), "+f"(c[2]), "+f"(c[3])
        : "r"(a[0]), "r"(a[1]), "r"(a[2]), "r"(a[3]), "r"(b0), "r"(b1));
}
#define ONESB 0x3F803F80u

// ---------------- kernel 1: WH = h @ W (fp32 exact) ----------------
__global__ void gemm_wh(const float* __restrict__ h, const float* __restrict__ Wm) {
    __shared__ float hs[64][36];
    __shared__ float Ws[32][68];
    const int tid = threadIdx.x;
    const int ibase = blockIdx.x * 64;
    const int tx = tid & 15, ty = tid >> 4;
    const int r0 = ty * 4, c0 = tx * 4;
    float acc[4][4] = {};
    for (int kt = 0; kt < INF; kt += 32) {
        __syncthreads();
#pragma unroll
        for (int q = 0; q < 2; q++) {
            int idx = tid + q * 256;
            int row = idx >> 3, kq = idx & 7;
            *(float4*)&hs[row][kq * 4] = *(const float4*)&h[(size_t)(ibase + row) * INF + kt + kq * 4];
            int kr = idx >> 4, cq = idx & 15;
            *(float4*)&Ws[kr][cq * 4] = *(const float4*)&Wm[(size_t)(kt + kr) * OF + cq * 4];
        }
        __syncthreads();
#pragma unroll
        for (int k = 0; k < 32; k++) {
            float4 b = *(const float4*)&Ws[k][c0];
#pragma unroll
            for (int r = 0; r < 4; r++) {
                float av = hs[r0 + r][k];
                acc[r][0] += av * b.x; acc[r][1] += av * b.y;
                acc[r][2] += av * b.z; acc[r][3] += av * b.w;
            }
        }
    }
#pragma unroll
    for (int r = 0; r < 4; r++)
        *(float4*)&g_WH[(size_t)(ibase + r0 + r) * OF + c0] =
            make_float4(acc[r][0], acc[r][1], acc[r][2], acc[r][3]);
}

// ---------------- kernel 2: per-row stats (factored exp trick) ----------------
__global__ void row_stats(const float* __restrict__ a) {
    const int lane = threadIdx.x & 31;
    const int wid = threadIdx.x >> 5;
    const int row = blockIdx.x * 8 + wid;
    float v0 = g_WH[row * OF + lane];
    float v1 = g_WH[row * OF + 32 + lane];
    float p1 = v0 * a[lane] + v1 * a[lane + 32];
    float p2 = v0 * a[64 + lane] + v1 * a[96 + lane];
#pragma unroll
    for (int off = 16; off; off >>= 1) {
        p1 += __shfl_xor_sync(0xffffffffu, p1, off);
        p2 += __shfl_xor_sync(0xffffffffu, p2, off);
    }
    if (lane == 0) {
        g_wh1[row] = p1; g_wh2[row] = p2;
        g_e1[row] = expf(p1); g_f1[row] = expf(0.01f * p1);
        g_e2[row] = expf(p2); g_f2[row] = expf(0.01f * p2);
    }
}

// ---------------- kernel 2b: B (=WH) -> mma fragments, bf16 hi/lo ----------------
__global__ void wht_prep() {
    int t = blockIdx.x * 256 + threadIdx.x;        // 0 .. 131071
    int lane = t & 31;
    int n = (t >> 5) & 7;
    int s = (t >> 8) & 1;
    int c = t >> 9;
    int j0 = c * 32 + s * 16 + 2 * (lane & 3);
    int f = n * 8 + (lane >> 2);
    float v00 = g_WH[(size_t)j0 * OF + f];
    float v01 = g_WH[(size_t)(j0 + 1) * OF + f];
    float v10 = g_WH[(size_t)(j0 + 8) * OF + f];
    float v11 = g_WH[(size_t)(j0 + 9) * OF + f];
    uint32_t bh0, bl0, bh1, bl1;
    split2(v00, v01, bh0, bl0);
    split2(v10, v11, bh1, bl1);
    g_Bf[t] = make_uint4(bh0, bh1, bl0, bl1);
}

// ---------------- kernel 3: fragment-direct fused attention GEMM ----------------
// warp owns 16 rows; B fragments staged in smem (double-buffered, shared by the
// 4 warps); per-j params hoisted to smem once; adjacency prefetched 1 tile ahead.
__global__ void __launch_bounds__(128, 4) attn(const int* __restrict__ adj) {
    __shared__ uint4 sB[2][512];                 // 16KB: B frags for current/next tile
    __shared__ float sW2[JCHUNK], sE2[JCHUNK], sF2[JCHUNK];   // 12KB params

    const int tid = threadIdx.x;
    const int lane = tid & 31;
    const int warp = tid >> 5;
    const int ibase = blockIdx.x * 64;
    const int split = blockIdx.y;
    const int g = lane >> 2, qp = lane & 3;
    const int rg = ibase + warp * 16 + g;
    const int rg8 = rg + 8;
    const int jbase = split * JCHUNK;

    // ---- one-time staging: params for the whole j-chunk ----
#pragma unroll
    for (int q = 0; q < 2; q++) {
        int idx = (tid + q * 128) * 4;           // 0..1023 floats, float4 granular
        *(float4*)&sW2[idx] = *(const float4*)&g_wh2[jbase + idx];
        *(float4*)&sE2[idx] = *(const float4*)&g_e2[jbase + idx];
        *(float4*)&sF2[idx] = *(const float4*)&g_f2[jbase + idx];
    }
    // stage B tile 0 into buffer 0
    {
        const uint4* bsrc = g_Bf + (size_t)(jbase >> 5) * 512;
#pragma unroll
        for (int q = 0; q < 4; q++) sB[0][tid + q * 128] = bsrc[tid + q * 128];
    }

    const float rwa = g_wh1[rg], rea = g_e1[rg], rfa = g_f1[rg];
    const float rwb = g_wh1[rg8], reb = g_e1[rg8], rfb = g_f1[rg8];

    float acc[8][4];
    float den[4];
#pragma unroll
    for (int n = 0; n < 8; n++)
#pragma unroll
        for (int q = 0; q < 4; q++) acc[n][q] = 0.f;
#pragma unroll
    for (int q = 0; q < 4; q++) den[q] = 0.f;

    const int* apA = adj + (size_t)rg * NN + 2 * qp;
    const int* apB = adj + (size_t)rg8 * NN + 2 * qp;

    int2 av[2][4];
#pragma unroll
    for (int u = 0; u < 4; u++) {
        av[0][u] = __ldcs((const int2*)(apA + jbase + u * 8));
        av[1][u] = __ldcs((const int2*)(apB + jbase + u * 8));
    }
    __syncthreads();                             // params + B tile 0 visible

    for (int t = 0; t < NKT; t++) {
        const int jt = jbase + t * 32;
        const int tn = (t + 1 < NKT) ? t + 1 : 0;
        const int jn = jbase + tn * 32;
        const int cb = t & 1;

        // prefetch next adjacency tile (consumed next iteration)
        int2 avn[2][4];
#pragma unroll
        for (int u = 0; u < 4; u++) {
            avn[0][u] = __ldcs((const int2*)(apA + jn + u * 8));
            avn[1][u] = __ldcs((const int2*)(apB + jn + u * 8));
        }
        // prefetch next B tile into registers (STS after compute)
        uint4 bstg[4];
        {
            const uint4* bsrc = g_Bf + (size_t)(jn >> 5) * 512;
#pragma unroll
            for (int q = 0; q < 4; q++) bstg[q] = bsrc[tid + q * 128];
        }

        const uint4* bp = sB[cb];
        const int jl = t * 32;                   // chunk-local j offset

#pragma unroll
        for (int s = 0; s < 2; s++) {
            const int c0 = jl + s * 16 + 2 * qp;
            float2 w2a = *(const float2*)&sW2[c0];
            float2 e2a = *(const float2*)&sE2[c0];
            float2 f2a = *(const float2*)&sF2[c0];
            float2 w2b = *(const float2*)&sW2[c0 + 8];
            float2 e2b = *(const float2*)&sE2[c0 + 8];
            float2 f2b = *(const float2*)&sF2[c0 + 8];

            uint32_t Ah[4], Al[4];
            wpair(av[0][2 * s],     rwa, rea, rfa, w2a, e2a, f2a, Ah[0], Al[0]);
            wpair(av[1][2 * s],     rwb, reb, rfb, w2a, e2a, f2a, Ah[1], Al[1]);
            wpair(av[0][2 * s + 1], rwa, rea, rfa, w2b, e2b, f2b, Ah[2], Al[2]);
            wpair(av[1][2 * s + 1], rwb, reb, rfb, w2b, e2b, f2b, Ah[3], Al[3]);

#pragma unroll
            for (int n = 0; n < 4; n++) {
                uint4 B = bp[(s * 8 + n) * 32 + lane];
                mma_bf16(acc[n], Ah, B.x, B.y);
                mma_bf16(acc[n], Al, B.x, B.y);
                mma_bf16(acc[n], Ah, B.z, B.w);
            }
            mma_bf16(den, Ah, ONESB, ONESB);
            mma_bf16(den, Al, ONESB, ONESB);
#pragma unroll
            for (int n = 0; n < 4; n++) {
                uint4 B = bp[(s * 8 + 4 + n) * 32 + lane];
                mma_bf16(acc[4 + n], Ah, B.x, B.y);
                mma_bf16(acc[4 + n], Al, B.x, B.y);
                mma_bf16(acc[4 + n], Ah, B.z, B.w);
            }
        }

        // commit staged B for next tile, then sync (read-done + write-visible)
        uint4* bdst = (uint4*)sB[cb ^ 1];
#pragma unroll
        for (int q = 0; q < 4; q++) bdst[tid + q * 128] = bstg[q];
#pragma unroll
        for (int u = 0; u < 4; u++) { av[0][u] = avn[0][u]; av[1][u] = avn[1][u]; }
        __syncthreads();
    }

    // ---- epilogue ----
    if (qp == 0) {
        g_den[split * NN + rg] = den[0];
        g_den[split * NN + rg8] = den[2];
    }
#pragma unroll
    for (int n = 0; n < 8; n++) {
        size_t ba = ((size_t)split * NN + rg) * OF + n * 8 + qp * 2;
        *(float2*)&g_num[ba] = make_float2(acc[n][0], acc[n][1]);
        *(float2*)&g_num[ba + 8 * (size_t)OF] = make_float2(acc[n][2], acc[n][3]);
    }
}

// ---------------- kernel 4: reduce partials, divide, ELU ----------------
__global__ void finalize_k(float* __restrict__ out) {
    int idx = blockIdx.x * 256 + threadIdx.x;
    int i = idx >> 6, f = idx & 63;
    float num = 0.f, den = 0.f;
#pragma unroll
    for (int s = 0; s < SPLITJ; s++) {
        num += g_num[((size_t)s * NN + i) * OF + f];
        den += g_den[s * NN + i];
    }
    float x = num / den;
    out[idx] = (x > 0.f) ? x : expm1f(x);
}

// ---------------- launch ----------------
extern "C" void kernel_launch(void* const* d_in, const int* in_sizes, int n_in,
                              void* d_out, int out_size) {
    const float* h = nullptr; const int* adj = nullptr;
    const float* Wm = nullptr; const float* a = nullptr;
    for (int i = 0; i < n_in; i++) {
        switch (in_sizes[i]) {
            case NN * INF: h = (const float*)d_in[i]; break;
            case NN * NN:  adj = (const int*)d_in[i]; break;
            case INF * OF: Wm = (const float*)d_in[i]; break;
            case 2 * OF:   a = (const float*)d_in[i]; break;
            default: break;
        }
    }
    gemm_wh<<<NN / 64, 256>>>(h, Wm);
    row_stats<<<NN / 8, 256>>>(a);
    wht_prep<<<512, 256>>>();
    dim3 g(NN / 64, SPLITJ);
    attn<<<g, 128>>>(adj);
    finalize_k<<<(NN * OF) / 256, 256>>>((float*)d_out);
}